// round 15
// baseline (speedup 1.0000x reference)
#include <cuda_runtime.h>
#include <cuda_fp16.h>
#include <cstdint>

#define BATCH 2
#define HEADS 16
#define SEQ   2048
#define DIM   1024
#define HDIM  64
#define MTOT  (BATCH*SEQ)   // 4096
#define QSCALE 0.18033688011112043f   // HDIM^-0.5 * log2(e)
#define NQB   (SEQ/128)     // 16 query blocks per (b,h)

// Scratch (device globals: allocation-free rule)
__device__ __half g_xh[MTOT*DIM];              // x in fp16
__device__ __half g_wh[4*DIM*DIM];             // Wq|Wk|Wv|Wo in fp16
__device__ __half g_q[BATCH*HEADS*SEQ*HDIM];   // [b,h,s,dh], pre-scaled by QSCALE
__device__ __half g_k[BATCH*HEADS*SEQ*HDIM];
__device__ __half g_v[BATCH*HEADS*SEQ*HDIM];
__device__ __half g_aoh[MTOT*DIM];             // scrambled attn output (fp16)
__device__ float  g_tsum[BATCH*HEADS*32*HDIM]; // per-tile V column sums

// ---------------------------------------------------------------------------
// helpers
// ---------------------------------------------------------------------------
__device__ __forceinline__ uint32_t smem_u32(const void* p) {
    uint32_t a;
    asm("{ .reg .u64 t; cvta.to.shared.u64 t, %1; cvt.u32.u64 %0, t; }"
        : "=r"(a) : "l"(p));
    return a;
}
#define LDSM_X4(r0,r1,r2,r3,addr) \
    asm volatile("ldmatrix.sync.aligned.m8n8.x4.shared.b16 {%0,%1,%2,%3}, [%4];" \
        : "=r"(r0),"=r"(r1),"=r"(r2),"=r"(r3) : "r"(addr))
#define LDSM_X4_T(r0,r1,r2,r3,addr) \
    asm volatile("ldmatrix.sync.aligned.m8n8.x4.trans.shared.b16 {%0,%1,%2,%3}, [%4];" \
        : "=r"(r0),"=r"(r1),"=r"(r2),"=r"(r3) : "r"(addr))
#define CP16(smem, gptr) \
    asm volatile("cp.async.cg.shared.global [%0], [%1], 16;" :: "r"(smem), "l"(gptr))
#define CP_COMMIT() asm volatile("cp.async.commit_group;")
#define CP_WAIT(n)  asm volatile("cp.async.wait_group %0;" :: "n"(n))

__device__ __forceinline__ void mma_h(float c[4], const uint32_t a[4], const uint32_t b[2]) {
    asm volatile(
        "mma.sync.aligned.m16n8k16.row.col.f32.f16.f16.f32 "
        "{%0,%1,%2,%3}, {%4,%5,%6,%7}, {%8,%9}, {%0,%1,%2,%3};"
        : "+f"(c[0]), "+f"(c[1]), "+f"(c[2]), "+f"(c[3])
        : "r"(a[0]), "r"(a[1]), "r"(a[2]), "r"(a[3]), "r"(b[0]), "r"(b[1]));
}
__device__ __forceinline__ uint32_t packh2(float a, float b) {
    __half2 h = __floats2half2_rn(a, b);
    return *(uint32_t*)&h;
}

// ---------------------------------------------------------------------------
// one-shot f32 -> fp16 conversion of x and the four weight matrices
// ---------------------------------------------------------------------------
__global__ __launch_bounds__(256) void convert_h(
    const float* __restrict__ x,
    const float* __restrict__ wq, const float* __restrict__ wk,
    const float* __restrict__ wv, const float* __restrict__ wo,
    __half* __restrict__ xh, __half* __restrict__ wh)
{
    size_t t = (size_t)blockIdx.x * 256 + threadIdx.x;
    size_t base = t * 8;
    unsigned seg = (unsigned)(base >> 20);
    const float* src;
    __half* dst;
    if (seg < 4) { src = x + base; dst = xh + base; }
    else {
        size_t off = base - ((size_t)seg << 20);
        const float* w = (seg == 4) ? wq : (seg == 5) ? wk : (seg == 6) ? wv : wo;
        src = w + off;
        dst = wh + (base - ((size_t)4 << 20));
    }
    float4 a = *(const float4*)src;
    float4 b = *(const float4*)(src + 4);
    __half2 h[4] = {__floats2half2_rn(a.x, a.y), __floats2half2_rn(a.z, a.w),
                    __floats2half2_rn(b.x, b.y), __floats2half2_rn(b.z, b.w)};
    *(uint4*)dst = *(uint4*)h;
}

// ---------------------------------------------------------------------------
// per-tile V column sums: T[bh][kt][dh] = sum over the 64 keys of tile kt
// ---------------------------------------------------------------------------
__global__ __launch_bounds__(64) void tilesum_k(
    const __half* __restrict__ v, float* __restrict__ T)
{
    const int kt = blockIdx.x, bh = blockIdx.y, dh = threadIdx.x;
    const __half* vp = v + ((size_t)bh * SEQ + kt * 64) * HDIM + dh;
    float acc = 0.f;
    #pragma unroll
    for (int j = 0; j < 64; j++) acc += __half2float(vp[(size_t)j * HDIM]);
    T[((size_t)bh * 32 + kt) * HDIM + dh] = acc;
}

// ---------------------------------------------------------------------------
// fp16 GEMM (cp.async 3-stage, fat warps): C = A(fp16) @ W^T(fp16) + bias
// CTA tile 128x128, BK=64, 128 threads, 4 warps in 2x2 (warp tile 64x64).
// Per k=16 step: 8 LDSM -> 32 mma (2x the old mma/LDSM ratio).
// mode 0: scatter fp16 into [b,h,s,dh] (z==0 output scaled by QSCALE);
// mode 1: f32 row-major.
// ---------------------------------------------------------------------------
#define BK     64
#define GST    72
#define GSTAGE (128*GST)            // halves per operand per stage
#define GSMEM  (6*GSTAGE*2)         // 3 stages x (A+W) = 110592 B

__global__ __launch_bounds__(128, 2) void gemm_h(
    const __half* __restrict__ A, const __half* __restrict__ Wb,
    const float* __restrict__ B0, const float* __restrict__ B1, const float* __restrict__ B2,
    __half* __restrict__ H0, __half* __restrict__ H1, __half* __restrict__ H2,
    float* __restrict__ Cf, int mode)
{
    extern __shared__ __half smg[];
    __half* As = smg;
    __half* Ws = smg + 3 * GSTAGE;

    const int z = blockIdx.z;
    const __half* W = Wb + (size_t)z * (DIM * DIM);
    const float* Bi = (z == 0) ? B0 : ((z == 1) ? B1 : B2);
    __half* Ho      = (z == 0) ? H0 : ((z == 1) ? H1 : H2);
    const float osc = (mode == 0 && z == 0) ? QSCALE : 1.0f;

    const int tid = threadIdx.x, lane = tid & 31, wid = tid >> 5;
    const int g = lane >> 2, tg = lane & 3;
    const int m0 = blockIdx.y * 128, n0 = blockIdx.x * 128;
    const int wm0 = (wid >> 1) * 64, wn0 = (wid & 1) * 64;

    float acc[4][8][4];
    #pragma unroll
    for (int mt = 0; mt < 4; mt++)
        #pragma unroll
        for (int nt = 0; nt < 8; nt++)
            #pragma unroll
            for (int r = 0; r < 4; r++) acc[mt][nt][r] = 0.f;

    const uint32_t aBase = smem_u32(As), wBase = smem_u32(Ws);

    auto load_stage = [&](int st, int kb) {
        const __half* Ag = A + (size_t)m0 * DIM + kb * BK;
        const __half* Wg = W + (size_t)n0 * DIM + kb * BK;
        uint32_t sa = aBase + (uint32_t)(st * GSTAGE) * 2;
        uint32_t sw = wBase + (uint32_t)(st * GSTAGE) * 2;
        #pragma unroll
        for (int i = 0; i < 8; i++) {
            int c = tid + i * 128;           // 0..1023
            int row = c >> 3, cc = (c & 7) * 8;
            uint32_t so = (uint32_t)(row * GST + cc) * 2;
            CP16(sa + so, Ag + (size_t)row * DIM + cc);
            CP16(sw + so, Wg + (size_t)row * DIM + cc);
        }
        CP_COMMIT();
    };

    const uint32_t aLane = (uint32_t)(((wm0 + (lane & 15)) * GST + (lane >> 4) * 8) * 2);
    const int bRow = (lane & 7) + ((lane & 16) ? 8 : 0);
    const int bColH = (lane & 8) ? 8 : 0;
    const uint32_t bLane = (uint32_t)(((wn0 + bRow) * GST + bColH) * 2);
    const uint32_t stageB = (uint32_t)GSTAGE * 2;

    load_stage(0, 0);
    load_stage(1, 1);

    const int NKB = DIM / BK;   // 16
    for (int kb = 0; kb < NKB; kb++) {
        const int cur = kb % 3;
        if (kb >= NKB - 2) { CP_WAIT(0); } else { CP_WAIT(1); }
        __syncthreads();
        if (kb + 2 < NKB) load_stage((kb + 2) % 3, kb + 2);

        const uint32_t aS = aBase + cur * stageB + aLane;
        const uint32_t bS = wBase + cur * stageB + bLane;
        #pragma unroll
        for (int ks = 0; ks < 4; ks++) {
            uint32_t af[4][4], bf[8][2];
            #pragma unroll
            for (int mt = 0; mt < 4; mt++)
                LDSM_X4(af[mt][0], af[mt][1], af[mt][2], af[mt][3],
                        aS + (uint32_t)((mt * 16 * GST + ks * 16) * 2));
            #pragma unroll
            for (int np = 0; np < 4; np++)
                LDSM_X4(bf[np*2][0], bf[np*2][1], bf[np*2+1][0], bf[np*2+1][1],
                        bS + (uint32_t)((np * 16 * GST + ks * 16) * 2));
            #pragma unroll
            for (int mt = 0; mt < 4; mt++)
                #pragma unroll
                for (int nt = 0; nt < 8; nt++)
                    mma_h(acc[mt][nt], af[mt], bf[nt]);
        }
    }

    __syncthreads();
    // epilogue
    #pragma unroll
    for (int mt = 0; mt < 4; mt++) {
        #pragma unroll
        for (int nt = 0; nt < 8; nt++) {
            int col = n0 + wn0 + nt * 8 + tg * 2;
            float b0v = Bi[col], b1v = Bi[col + 1];
            #pragma unroll
            for (int h2 = 0; h2 < 2; h2++) {
                int row = m0 + wm0 + mt * 16 + g + h2 * 8;
                float v0 = (acc[mt][nt][h2*2 + 0] + b0v) * osc;
                float v1 = (acc[mt][nt][h2*2 + 1] + b1v) * osc;
                if (mode == 0) {
                    int b = row >> 11, s = row & 2047;
                    int hh = col >> 6, dh = col & 63;
                    size_t idx = (((size_t)(b * HEADS + hh)) * SEQ + s) * HDIM + dh;
                    *(__half2*)(Ho + idx) = __floats2half2_rn(v0, v1);
                } else {
                    *(float2*)(Cf + (size_t)row * DIM + col) = make_float2(v0, v1);
                }
            }
        }
    }
}

// ---------------------------------------------------------------------------
// fp16 attention, fat warps: 128 threads, 4 warps, warp = 32 query rows.
// K/V fragments loaded once per warp feed 2x the mma (mma/LDSM 2.1 -> 4.25).
// Causal tile skipping + ex2.f16x2 softmax + mma rowsums + LPT schedule +
// 128-key pipeline iterations. 296 CTAs, 1-2 (bh,iq) items each.
// smem halves: Q[128][72] | K[2][128][72] | V[2][128][72] | suf (64 floats)
// ---------------------------------------------------------------------------
#define AST     72
#define AQ_OFF  0
#define AK_OFF  (128*AST)
#define AV_OFF  (AK_OFF + 2*128*AST)
#define AH_TOT  (AV_OFF + 2*128*AST)
#define ASMEM   (AH_TOT*2 + 64*4)
#define NCTA_A  296

__global__ __launch_bounds__(128, 2) void attn_h(
    const __half* __restrict__ q, const __half* __restrict__ k,
    const __half* __restrict__ v, const float* __restrict__ Tsum,
    __half* __restrict__ ao)
{
    extern __shared__ __half sma[];
    float* suf = (float*)(sma + AH_TOT);

    const int tid = threadIdx.x, lane = tid & 31, wid = tid >> 5;
    const int g = lane >> 2, tg = lane & 3;
    const int j = blockIdx.x;
    const int nitems = (j < 80) ? 1 : 2;

    const uint32_t sBase = smem_u32(sma);
    const int bRowL = (lane & 7) + ((lane & 16) ? 8 : 0);
    const int bColH = (lane & 8) ? 8 : 0;
    const int vRowL = (lane & 7) + ((lane & 8) ? 8 : 0);
    const int vColH = (lane & 16) ? 8 : 0;
    const uint32_t stB  = (uint32_t)(128 * AST * 2);   // bytes per 128-row stage
    const uint32_t subB = (uint32_t)(64 * AST * 2);    // bytes per 64-row subtile
    const uint32_t kB0 = sBase + (uint32_t)((AK_OFF + bRowL * AST + bColH) * 2);
    const uint32_t vB0 = sBase + (uint32_t)((AV_OFF + vRowL * AST + vColH) * 2);
    const uint32_t onesb[2] = {0x3C003C00u, 0x3C003C00u};

    for (int it = 0; it < nitems; it++) {
        const int r  = (it == 0) ? j : (591 - j);
        const int bh = r & 31;
        const int iq = 15 - (r >> 5);
        const int b  = bh >> 4, h = bh & 15;
        const int q0 = iq * 128;
        const int ktEnd = 2 * iq + 2;      // 64-key tiles
        const int nIter = iq + 1;          // 128-key iterations

        const __half* qp = q + (size_t)bh * SEQ * HDIM;
        const __half* kp = k + (size_t)bh * SEQ * HDIM;
        const __half* vp = v + (size_t)bh * SEQ * HDIM;

        if (it > 0) __syncthreads();   // protect smem reuse across items

        // 128-key K/V stage loader: 8 K-chunks + 8 V-chunks per thread
        auto load_kv = [&](int st, int itk) {
            const __half* Kg = kp + (size_t)(itk * 128) * HDIM;
            const __half* Vg = vp + (size_t)(itk * 128) * HDIM;
            uint32_t sk = sBase + (uint32_t)(AK_OFF + st * 128 * AST) * 2;
            uint32_t sv = sBase + (uint32_t)(AV_OFF + st * 128 * AST) * 2;
            #pragma unroll
            for (int i = 0; i < 8; i++) {
                int c = tid + i * 128;       // 0..1023
                int row = c >> 3, cc = (c & 7) * 8;
                uint32_t so = (uint32_t)(row * AST + cc) * 2;
                CP16(sk + so, Kg + (size_t)row * HDIM + cc);
                CP16(sv + so, Vg + (size_t)row * HDIM + cc);
            }
            CP_COMMIT();
        };

        // prologue: Q tile (1024 chunks over 128 threads) + K/V stage 0
        {
            #pragma unroll
            for (int i = 0; i < 8; i++) {
                int c = tid + i * 128;
                int row = c >> 3, cc = (c & 7) * 8;
                CP16(sBase + (uint32_t)(AQ_OFF + row * AST + cc) * 2,
                     qp + (size_t)(q0 + row) * HDIM + cc);
            }
        }
        load_kv(0, 0);

        // V column suffix sum over masked tiles (overlaps cp.async)
        if (tid < 64) {
            float acc = 0.f;
            const float* tp = Tsum + ((size_t)bh * 32) * HDIM + tid;
            for (int kt = ktEnd; kt < 32; kt++) acc += tp[(size_t)kt * HDIM];
            suf[tid] = acc;
        }

        CP_WAIT(0);
        __syncthreads();

        // persistent Q fragments: warp rows [wid*32, wid*32+32), 2 row groups
        uint32_t qf2[2][4][4];
        {
            const uint32_t qA = sBase +
                (uint32_t)((AQ_OFF + (wid * 32 + (lane & 15)) * AST + (lane >> 4) * 8) * 2);
            #pragma unroll
            for (int mt = 0; mt < 2; mt++)
                #pragma unroll
                for (int ks = 0; ks < 4; ks++)
                    LDSM_X4(qf2[mt][ks][0], qf2[mt][ks][1], qf2[mt][ks][2], qf2[mt][ks][3],
                            qA + (uint32_t)((mt * 16 * AST + ks * 16) * 2));
        }

        if (nIter > 1) load_kv(1, 1);

        float o[2][8][4];
        float rsacc[2][4];
        #pragma unroll
        for (int mt = 0; mt < 2; mt++) {
            #pragma unroll
            for (int rr = 0; rr < 4; rr++) rsacc[mt][rr] = 0.f;
            #pragma unroll
            for (int nt = 0; nt < 8; nt++)
                #pragma unroll
                for (int rr = 0; rr < 4; rr++) o[mt][nt][rr] = 0.f;
        }

        for (int itk = 0; itk < nIter; itk++) {
            const int cur = itk & 1;
            if (itk > 0) {
                CP_WAIT(0);
                __syncthreads();
                if (itk + 1 < nIter) load_kv(cur ^ 1, itk + 1);
            }

            #pragma unroll
            for (int sub = 0; sub < 2; sub++) {
                const int kt64 = itk * 2 + sub;
                const int k0t = kt64 * 64;

                // S = Qs @ K^T for both 16-row groups off one K-fragment load
                float s[2][8][4];
                #pragma unroll
                for (int mt = 0; mt < 2; mt++)
                    #pragma unroll
                    for (int nt = 0; nt < 8; nt++)
                        #pragma unroll
                        for (int rr = 0; rr < 4; rr++) s[mt][nt][rr] = 0.f;
                {
                    const uint32_t kB = kB0 + cur * stB + sub * subB;
                    #pragma unroll
                    for (int ks = 0; ks < 4; ks++) {
                        uint32_t bf[8][2];
                        #pragma unroll
                        for (int np = 0; np < 4; np++)
                            LDSM_X4(bf[np*2][0], bf[np*2][1], bf[np*2+1][0], bf[np*2+1][1],
                                    kB + (uint32_t)((np * 16 * AST + ks * 16) * 2));
                        #pragma unroll
                        for (int mt = 0; mt < 2; mt++)
                            #pragma unroll
                            for (int nt = 0; nt < 8; nt++)
                                mma_h(s[mt][nt], qf2[mt][ks], bf[nt]);
                    }
                }

                // softmax: pack -> ex2.approx.f16x2 -> PV A-fragments.
                // mask (x=0 -> P=1.0) only on diagonal-touching tiles.
                const bool diag = (kt64 + 2 >= ktEnd);
                uint32_t pf[2][4][4];
                #pragma unroll
                for (int mt = 0; mt < 2; mt++) {
                    const int row0m = q0 + wid * 32 + mt * 16 + g;
                    #pragma unroll
                    for (int nt = 0; nt < 8; nt++) {
                        float x0 = s[mt][nt][0], x1 = s[mt][nt][1];
                        float x2 = s[mt][nt][2], x3 = s[mt][nt][3];
                        if (diag) {
                            int colj = k0t + nt * 8 + tg * 2;
                            x0 = (colj     > row0m    ) ? 0.f : x0;
                            x1 = (colj + 1 > row0m    ) ? 0.f : x1;
                            x2 = (colj     > row0m + 8) ? 0.f : x2;
                            x3 = (colj + 1 > row0m + 8) ? 0.f : x3;
                        }
                        uint32_t h01 = packh2(x0, x1), h23 = packh2(x2, x3);
                        uint32_t p01, p23;
                        asm("ex2.approx.f16x2 %0, %1;" : "=r"(p01) : "r"(h01));
                        asm("ex2.approx.f16x2 %0, %1;" : "=r"(p23) : "r"(h23));
                        pf[mt][nt >> 1][(nt & 1) * 2 + 0] = p01;
                        pf[mt][nt >> 1][(nt & 1) * 2 + 1] = p23;
                    }
                }

                // O += P @ V for both row groups off one V-fragment load
                {
                    const uint32_t vB = vB0 + cur * stB + sub * subB;
                    #pragma unroll
                    for (int kp2 = 0; kp2 < 4; kp2++) {
                        uint32_t vf[8][2];
                        #pragma unroll
                        for (int np = 0; np < 4; np++)
                            LDSM_X4_T(vf[np*2][0], vf[np*2][1], vf[np*2+1][0], vf[np*2+1][1],
                                      vB + (uint32_t)((kp2 * 16 * AST + np * 16) * 2));
                        #pragma unroll
                        for (int mt = 0; mt < 2; mt++) {
                            #pragma unroll
                            for (int nt = 0; nt < 8; nt++)
                                mma_h(o[mt][nt], pf[mt][kp2], vf[nt]);
                            mma_h(rsacc[mt], pf[mt][kp2], onesb);
                        }
                    }
                }
            }
        }

        const float nmask = (float)(SEQ - ktEnd * 64);

        #pragma unroll
        for (int mt = 0; mt < 2; mt++) {
            // masked-tile contribution (P==1): suffix column sums of V
            #pragma unroll
            for (int nt = 0; nt < 8; nt++) {
                #pragma unroll
                for (int c2 = 0; c2 < 2; c2++) {
                    float sv = suf[nt * 8 + tg * 2 + c2];
                    o[mt][nt][c2]     += sv;
                    o[mt][nt][2 + c2] += sv;
                }
            }

            const float inv0 = 1.0f / (rsacc[mt][0] + nmask);
            const float inv1 = 1.0f / (rsacc[mt][2] + nmask);

            // normalize + scatter fp16 into scrambled layout:
            // [b,h,s,dh] -> ao[b][2c + (s>>10)][s & 1023], c = h*64+dh
            const int s0 = q0 + wid * 32 + mt * 16 + g, s1 = s0 + 8;
            #pragma unroll
            for (int nt = 0; nt < 8; nt++) {
                #pragma unroll
                for (int c2 = 0; c2 < 2; c2++) {
                    int dh = nt * 8 + tg * 2 + c2;
                    int c  = h * 64 + dh;
                    size_t rowb = (size_t)b * SEQ * DIM;
                    ao[rowb + (size_t)(2*c + (s0 >> 10)) * DIM + (s0 & 1023)] =
                        __float2half(o[mt][nt][c2] * inv0);
                    ao[rowb + (size_t)(2*c + (s1 >> 10)) * DIM + (s1 & 1023)] =
                        __float2half(o[mt][nt][2 + c2] * inv1);
                }
            }
        }
    }
}

// ---------------------------------------------------------------------------
extern "C" void kernel_launch(void* const* d_in, const int* in_sizes, int n_in,
                              void* d_out, int out_size)
{
    const float* x  = (const float*)d_in[0];
    const float* Wq = (const float*)d_in[2];
    const float* bq = (const float*)d_in[3];
    const float* Wk = (const float*)d_in[4];
    const float* bk = (const float*)d_in[5];
    const float* Wv = (const float*)d_in[6];
    const float* bv = (const float*)d_in[7];
    const float* Wo = (const float*)d_in[8];
    const float* bo = (const float*)d_in[9];
    float* out = (float*)d_out;

    __half *xh, *wh, *q, *k, *v, *aoh;
    float *ts;
    cudaGetSymbolAddress((void**)&xh,  g_xh);
    cudaGetSymbolAddress((void**)&wh,  g_wh);
    cudaGetSymbolAddress((void**)&q,   g_q);
    cudaGetSymbolAddress((void**)&k,   g_k);
    cudaGetSymbolAddress((void**)&v,   g_v);
    cudaGetSymbolAddress((void**)&aoh, g_aoh);
    cudaGetSymbolAddress((void**)&ts,  g_tsum);

    cudaFuncSetAttribute(gemm_h, cudaFuncAttributeMaxDynamicSharedMemorySize, GSMEM);
    cudaFuncSetAttribute(attn_h, cudaFuncAttributeMaxDynamicSharedMemorySize, ASMEM);

    convert_h<<<4096, 256>>>(x, Wq, Wk, Wv, Wo, xh, wh);

    // fused QKV projections (tile 128x128, fat warps 64x64, 4 warps)
    dim3 gg(DIM / 128, MTOT / 128, 3);   // (8, 32, 3)
    gemm_h<<<gg, 128, GSMEM>>>(xh, wh, bq, bk, bv, q, k, v, nullptr, 0);

    dim3 gt(32, BATCH * HEADS);          // per-tile V column sums
    tilesum_k<<<gt, 64>>>(v, ts);

    attn_h<<<NCTA_A, 128, ASMEM>>>(q, k, v, ts, aoh);

    // output projection (f32 out)
    dim3 go(DIM / 128, MTOT / 128, 1);
    gemm_h<<<go, 128, GSMEM>>>(aoh, wh + 3 * (size_t)DIM * DIM,
                               bo, bo, bo, q, q, q, out, 1);
}

// round 16
// speedup vs baseline: 1.0108x; 1.0108x over previous
#include <cuda_runtime.h>
#include <cuda_fp16.h>
#include <cstdint>

#define BATCH 2
#define HEADS 16
#define SEQ   2048
#define DIM   1024
#define HDIM  64
#define MTOT  (BATCH*SEQ)   // 4096
#define QSCALE 0.18033688011112043f   // HDIM^-0.5 * log2(e)
#define NQB   (SEQ/128)     // 16 query blocks per (b,h)

// Scratch (device globals: allocation-free rule)
__device__ __half g_xh[MTOT*DIM];              // x in fp16
__device__ __half g_wh[4*DIM*DIM];             // Wq|Wk|Wv|Wo in fp16
__device__ __half g_q[BATCH*HEADS*SEQ*HDIM];   // [b,h,s,dh], pre-scaled by QSCALE
__device__ __half g_k[BATCH*HEADS*SEQ*HDIM];
__device__ __half g_v[BATCH*HEADS*SEQ*HDIM];
__device__ __half g_aoh[MTOT*DIM];             // scrambled attn output (fp16)
__device__ float  g_tsum[BATCH*HEADS*32*HDIM]; // per-tile V column sums

// ---------------------------------------------------------------------------
// helpers
// ---------------------------------------------------------------------------
__device__ __forceinline__ uint32_t smem_u32(const void* p) {
    uint32_t a;
    asm("{ .reg .u64 t; cvta.to.shared.u64 t, %1; cvt.u32.u64 %0, t; }"
        : "=r"(a) : "l"(p));
    return a;
}
#define LDSM_X4(r0,r1,r2,r3,addr) \
    asm volatile("ldmatrix.sync.aligned.m8n8.x4.shared.b16 {%0,%1,%2,%3}, [%4];" \
        : "=r"(r0),"=r"(r1),"=r"(r2),"=r"(r3) : "r"(addr))
#define LDSM_X4_T(r0,r1,r2,r3,addr) \
    asm volatile("ldmatrix.sync.aligned.m8n8.x4.trans.shared.b16 {%0,%1,%2,%3}, [%4];" \
        : "=r"(r0),"=r"(r1),"=r"(r2),"=r"(r3) : "r"(addr))
#define CP16(smem, gptr) \
    asm volatile("cp.async.cg.shared.global [%0], [%1], 16;" :: "r"(smem), "l"(gptr))
#define CP_COMMIT() asm volatile("cp.async.commit_group;")
#define CP_WAIT(n)  asm volatile("cp.async.wait_group %0;" :: "n"(n))

__device__ __forceinline__ void mma_h(float c[4], const uint32_t a[4], const uint32_t b[2]) {
    asm volatile(
        "mma.sync.aligned.m16n8k16.row.col.f32.f16.f16.f32 "
        "{%0,%1,%2,%3}, {%4,%5,%6,%7}, {%8,%9}, {%0,%1,%2,%3};"
        : "+f"(c[0]), "+f"(c[1]), "+f"(c[2]), "+f"(c[3])
        : "r"(a[0]), "r"(a[1]), "r"(a[2]), "r"(a[3]), "r"(b[0]), "r"(b[1]));
}
__device__ __forceinline__ uint32_t packh2(float a, float b) {
    __half2 h = __floats2half2_rn(a, b);
    return *(uint32_t*)&h;
}

// ---------------------------------------------------------------------------
// one-shot f32 -> fp16 conversion of x and the four weight matrices
// ---------------------------------------------------------------------------
__global__ __launch_bounds__(256) void convert_h(
    const float* __restrict__ x,
    const float* __restrict__ wq, const float* __restrict__ wk,
    const float* __restrict__ wv, const float* __restrict__ wo,
    __half* __restrict__ xh, __half* __restrict__ wh)
{
    size_t t = (size_t)blockIdx.x * 256 + threadIdx.x;
    size_t base = t * 8;
    unsigned seg = (unsigned)(base >> 20);
    const float* src;
    __half* dst;
    if (seg < 4) { src = x + base; dst = xh + base; }
    else {
        size_t off = base - ((size_t)seg << 20);
        const float* w = (seg == 4) ? wq : (seg == 5) ? wk : (seg == 6) ? wv : wo;
        src = w + off;
        dst = wh + (base - ((size_t)4 << 20));
    }
    float4 a = *(const float4*)src;
    float4 b = *(const float4*)(src + 4);
    __half2 h[4] = {__floats2half2_rn(a.x, a.y), __floats2half2_rn(a.z, a.w),
                    __floats2half2_rn(b.x, b.y), __floats2half2_rn(b.z, b.w)};
    *(uint4*)dst = *(uint4*)h;
}

// ---------------------------------------------------------------------------
// per-tile V column sums: T[bh][kt][dh] = sum over the 64 keys of tile kt
// ---------------------------------------------------------------------------
__global__ __launch_bounds__(64) void tilesum_k(
    const __half* __restrict__ v, float* __restrict__ T)
{
    const int kt = blockIdx.x, bh = blockIdx.y, dh = threadIdx.x;
    const __half* vp = v + ((size_t)bh * SEQ + kt * 64) * HDIM + dh;
    float acc = 0.f;
    #pragma unroll
    for (int j = 0; j < 64; j++) acc += __half2float(vp[(size_t)j * HDIM]);
    T[((size_t)bh * 32 + kt) * HDIM + dh] = acc;
}

// ---------------------------------------------------------------------------
// fp16 GEMM (R13 thin-warp form — best measured): C = A @ W^T + bias
// CTA tile 128x128, BK=64, 256 threads, 8 warps 2x4 (warp tile 64x32),
// 3-stage cp.async, one sync per iteration.
// mode 0: scatter fp16 into [b,h,s,dh] (z==0 output scaled by QSCALE);
// mode 1: f32 row-major.
// ---------------------------------------------------------------------------
#define BK     64
#define GST    72
#define GSTAGE (128*GST)            // halves per operand per stage
#define GSMEM  (6*GSTAGE*2)         // 3 stages x (A+W) = 110592 B

__global__ __launch_bounds__(256, 2) void gemm_h(
    const __half* __restrict__ A, const __half* __restrict__ Wb,
    const float* __restrict__ B0, const float* __restrict__ B1, const float* __restrict__ B2,
    __half* __restrict__ H0, __half* __restrict__ H1, __half* __restrict__ H2,
    float* __restrict__ Cf, int mode)
{
    extern __shared__ __half smg[];
    __half* As = smg;
    __half* Ws = smg + 3 * GSTAGE;

    const int z = blockIdx.z;
    const __half* W = Wb + (size_t)z * (DIM * DIM);
    const float* Bi = (z == 0) ? B0 : ((z == 1) ? B1 : B2);
    __half* Ho      = (z == 0) ? H0 : ((z == 1) ? H1 : H2);
    const float osc = (mode == 0 && z == 0) ? QSCALE : 1.0f;

    const int tid = threadIdx.x, lane = tid & 31, wid = tid >> 5;
    const int g = lane >> 2, tg = lane & 3;
    const int m0 = blockIdx.y * 128, n0 = blockIdx.x * 128;
    const int wm0 = (wid >> 2) * 64, wn0 = (wid & 3) * 32;

    float acc[4][4][4];
    #pragma unroll
    for (int mt = 0; mt < 4; mt++)
        #pragma unroll
        for (int nt = 0; nt < 4; nt++)
            #pragma unroll
            for (int r = 0; r < 4; r++) acc[mt][nt][r] = 0.f;

    const uint32_t aBase = smem_u32(As), wBase = smem_u32(Ws);
    const int ldRow = tid >> 3, ldCc = (tid & 7) * 8;

    auto load_stage = [&](int st, int kb) {
        const __half* Ag = A + (size_t)m0 * DIM + kb * BK;
        const __half* Wg = W + (size_t)n0 * DIM + kb * BK;
        uint32_t sa = aBase + (uint32_t)(st * GSTAGE) * 2;
        uint32_t sw = wBase + (uint32_t)(st * GSTAGE) * 2;
        #pragma unroll
        for (int i = 0; i < 4; i++) {
            int row = ldRow + i * 32;
            uint32_t so = (uint32_t)(row * GST + ldCc) * 2;
            CP16(sa + so, Ag + (size_t)row * DIM + ldCc);
            CP16(sw + so, Wg + (size_t)row * DIM + ldCc);
        }
        CP_COMMIT();
    };

    const uint32_t aLane = (uint32_t)(((wm0 + (lane & 15)) * GST + (lane >> 4) * 8) * 2);
    const int bRow = (lane & 7) + ((lane & 16) ? 8 : 0);
    const int bColH = (lane & 8) ? 8 : 0;
    const uint32_t bLane = (uint32_t)(((wn0 + bRow) * GST + bColH) * 2);
    const uint32_t stageB = (uint32_t)GSTAGE * 2;

    load_stage(0, 0);
    load_stage(1, 1);

    const int NKB = DIM / BK;   // 16
    for (int kb = 0; kb < NKB; kb++) {
        const int cur = kb % 3;
        if (kb >= NKB - 2) { CP_WAIT(0); } else { CP_WAIT(1); }
        __syncthreads();
        if (kb + 2 < NKB) load_stage((kb + 2) % 3, kb + 2);

        const uint32_t aS = aBase + cur * stageB + aLane;
        const uint32_t bS = wBase + cur * stageB + bLane;
        #pragma unroll
        for (int ks = 0; ks < 4; ks++) {
            uint32_t af[4][4], bf[4][2];
            #pragma unroll
            for (int mt = 0; mt < 4; mt++)
                LDSM_X4(af[mt][0], af[mt][1], af[mt][2], af[mt][3],
                        aS + (uint32_t)((mt * 16 * GST + ks * 16) * 2));
            #pragma unroll
            for (int np = 0; np < 2; np++)
                LDSM_X4(bf[np*2][0], bf[np*2][1], bf[np*2+1][0], bf[np*2+1][1],
                        bS + (uint32_t)((np * 16 * GST + ks * 16) * 2));
            #pragma unroll
            for (int mt = 0; mt < 4; mt++)
                #pragma unroll
                for (int nt = 0; nt < 4; nt++)
                    mma_h(acc[mt][nt], af[mt], bf[nt]);
        }
    }

    __syncthreads();
    // epilogue
    #pragma unroll
    for (int mt = 0; mt < 4; mt++) {
        #pragma unroll
        for (int nt = 0; nt < 4; nt++) {
            int col = n0 + wn0 + nt * 8 + tg * 2;
            float b0v = Bi[col], b1v = Bi[col + 1];
            #pragma unroll
            for (int h2 = 0; h2 < 2; h2++) {
                int row = m0 + wm0 + mt * 16 + g + h2 * 8;
                float v0 = (acc[mt][nt][h2*2 + 0] + b0v) * osc;
                float v1 = (acc[mt][nt][h2*2 + 1] + b1v) * osc;
                if (mode == 0) {
                    int b = row >> 11, s = row & 2047;
                    int hh = col >> 6, dh = col & 63;
                    size_t idx = (((size_t)(b * HEADS + hh)) * SEQ + s) * HDIM + dh;
                    *(__half2*)(Ho + idx) = __floats2half2_rn(v0, v1);
                } else {
                    *(float2*)(Cf + (size_t)row * DIM + col) = make_float2(v0, v1);
                }
            }
        }
    }
}

// ---------------------------------------------------------------------------
// fp16 attention (R15 fat-warp form — best measured): 128 threads, 4 warps,
// warp = 32 query rows; K/V fragments feed 2x mma per LDSM.
// Causal tile skipping + ex2.f16x2 softmax + mma rowsums + LPT schedule +
// 128-key pipeline iterations. 296 CTAs, 1-2 (bh,iq) items each.
// smem halves: Q[128][72] | K[2][128][72] | V[2][128][72] | suf (64 floats)
// ---------------------------------------------------------------------------
#define AST     72
#define AQ_OFF  0
#define AK_OFF  (128*AST)
#define AV_OFF  (AK_OFF + 2*128*AST)
#define AH_TOT  (AV_OFF + 2*128*AST)
#define ASMEM   (AH_TOT*2 + 64*4)
#define NCTA_A  296

__global__ __launch_bounds__(128, 2) void attn_h(
    const __half* __restrict__ q, const __half* __restrict__ k,
    const __half* __restrict__ v, const float* __restrict__ Tsum,
    __half* __restrict__ ao)
{
    extern __shared__ __half sma[];
    float* suf = (float*)(sma + AH_TOT);

    const int tid = threadIdx.x, lane = tid & 31, wid = tid >> 5;
    const int g = lane >> 2, tg = lane & 3;
    const int j = blockIdx.x;
    const int nitems = (j < 80) ? 1 : 2;

    const uint32_t sBase = smem_u32(sma);
    const int bRowL = (lane & 7) + ((lane & 16) ? 8 : 0);
    const int bColH = (lane & 8) ? 8 : 0;
    const int vRowL = (lane & 7) + ((lane & 8) ? 8 : 0);
    const int vColH = (lane & 16) ? 8 : 0;
    const uint32_t stB  = (uint32_t)(128 * AST * 2);   // bytes per 128-row stage
    const uint32_t subB = (uint32_t)(64 * AST * 2);    // bytes per 64-row subtile
    const uint32_t kB0 = sBase + (uint32_t)((AK_OFF + bRowL * AST + bColH) * 2);
    const uint32_t vB0 = sBase + (uint32_t)((AV_OFF + vRowL * AST + vColH) * 2);
    const uint32_t onesb[2] = {0x3C003C00u, 0x3C003C00u};

    for (int it = 0; it < nitems; it++) {
        const int r  = (it == 0) ? j : (591 - j);
        const int bh = r & 31;
        const int iq = 15 - (r >> 5);
        const int b  = bh >> 4, h = bh & 15;
        const int q0 = iq * 128;
        const int ktEnd = 2 * iq + 2;      // 64-key tiles
        const int nIter = iq + 1;          // 128-key iterations

        const __half* qp = q + (size_t)bh * SEQ * HDIM;
        const __half* kp = k + (size_t)bh * SEQ * HDIM;
        const __half* vp = v + (size_t)bh * SEQ * HDIM;

        if (it > 0) __syncthreads();   // protect smem reuse across items

        // 128-key K/V stage loader: 8 K-chunks + 8 V-chunks per thread
        auto load_kv = [&](int st, int itk) {
            const __half* Kg = kp + (size_t)(itk * 128) * HDIM;
            const __half* Vg = vp + (size_t)(itk * 128) * HDIM;
            uint32_t sk = sBase + (uint32_t)(AK_OFF + st * 128 * AST) * 2;
            uint32_t sv = sBase + (uint32_t)(AV_OFF + st * 128 * AST) * 2;
            #pragma unroll
            for (int i = 0; i < 8; i++) {
                int c = tid + i * 128;       // 0..1023
                int row = c >> 3, cc = (c & 7) * 8;
                uint32_t so = (uint32_t)(row * AST + cc) * 2;
                CP16(sk + so, Kg + (size_t)row * HDIM + cc);
                CP16(sv + so, Vg + (size_t)row * HDIM + cc);
            }
            CP_COMMIT();
        };

        // prologue: Q tile (1024 chunks over 128 threads) + K/V stage 0
        {
            #pragma unroll
            for (int i = 0; i < 8; i++) {
                int c = tid + i * 128;
                int row = c >> 3, cc = (c & 7) * 8;
                CP16(sBase + (uint32_t)(AQ_OFF + row * AST + cc) * 2,
                     qp + (size_t)(q0 + row) * HDIM + cc);
            }
        }
        load_kv(0, 0);

        // V column suffix sum over masked tiles (overlaps cp.async)
        if (tid < 64) {
            float acc = 0.f;
            const float* tp = Tsum + ((size_t)bh * 32) * HDIM + tid;
            for (int kt = ktEnd; kt < 32; kt++) acc += tp[(size_t)kt * HDIM];
            suf[tid] = acc;
        }

        CP_WAIT(0);
        __syncthreads();

        // persistent Q fragments: warp rows [wid*32, wid*32+32), 2 row groups
        uint32_t qf2[2][4][4];
        {
            const uint32_t qA = sBase +
                (uint32_t)((AQ_OFF + (wid * 32 + (lane & 15)) * AST + (lane >> 4) * 8) * 2);
            #pragma unroll
            for (int mt = 0; mt < 2; mt++)
                #pragma unroll
                for (int ks = 0; ks < 4; ks++)
                    LDSM_X4(qf2[mt][ks][0], qf2[mt][ks][1], qf2[mt][ks][2], qf2[mt][ks][3],
                            qA + (uint32_t)((mt * 16 * AST + ks * 16) * 2));
        }

        if (nIter > 1) load_kv(1, 1);

        float o[2][8][4];
        float rsacc[2][4];
        #pragma unroll
        for (int mt = 0; mt < 2; mt++) {
            #pragma unroll
            for (int rr = 0; rr < 4; rr++) rsacc[mt][rr] = 0.f;
            #pragma unroll
            for (int nt = 0; nt < 8; nt++)
                #pragma unroll
                for (int rr = 0; rr < 4; rr++) o[mt][nt][rr] = 0.f;
        }

        for (int itk = 0; itk < nIter; itk++) {
            const int cur = itk & 1;
            if (itk > 0) {
                CP_WAIT(0);
                __syncthreads();
                if (itk + 1 < nIter) load_kv(cur ^ 1, itk + 1);
            }

            #pragma unroll
            for (int sub = 0; sub < 2; sub++) {
                const int kt64 = itk * 2 + sub;
                const int k0t = kt64 * 64;

                // S = Qs @ K^T for both 16-row groups off one K-fragment load
                float s[2][8][4];
                #pragma unroll
                for (int mt = 0; mt < 2; mt++)
                    #pragma unroll
                    for (int nt = 0; nt < 8; nt++)
                        #pragma unroll
                        for (int rr = 0; rr < 4; rr++) s[mt][nt][rr] = 0.f;
                {
                    const uint32_t kB = kB0 + cur * stB + sub * subB;
                    #pragma unroll
                    for (int ks = 0; ks < 4; ks++) {
                        uint32_t bf[8][2];
                        #pragma unroll
                        for (int np = 0; np < 4; np++)
                            LDSM_X4(bf[np*2][0], bf[np*2][1], bf[np*2+1][0], bf[np*2+1][1],
                                    kB + (uint32_t)((np * 16 * AST + ks * 16) * 2));
                        #pragma unroll
                        for (int mt = 0; mt < 2; mt++)
                            #pragma unroll
                            for (int nt = 0; nt < 8; nt++)
                                mma_h(s[mt][nt], qf2[mt][ks], bf[nt]);
                    }
                }

                // softmax: pack -> ex2.approx.f16x2 -> PV A-fragments.
                // mask (x=0 -> P=1.0) only on diagonal-touching tiles.
                const bool diag = (kt64 + 2 >= ktEnd);
                uint32_t pf[2][4][4];
                #pragma unroll
                for (int mt = 0; mt < 2; mt++) {
                    const int row0m = q0 + wid * 32 + mt * 16 + g;
                    #pragma unroll
                    for (int nt = 0; nt < 8; nt++) {
                        float x0 = s[mt][nt][0], x1 = s[mt][nt][1];
                        float x2 = s[mt][nt][2], x3 = s[mt][nt][3];
                        if (diag) {
                            int colj = k0t + nt * 8 + tg * 2;
                            x0 = (colj     > row0m    ) ? 0.f : x0;
                            x1 = (colj + 1 > row0m    ) ? 0.f : x1;
                            x2 = (colj     > row0m + 8) ? 0.f : x2;
                            x3 = (colj + 1 > row0m + 8) ? 0.f : x3;
                        }
                        uint32_t h01 = packh2(x0, x1), h23 = packh2(x2, x3);
                        uint32_t p01, p23;
                        asm("ex2.approx.f16x2 %0, %1;" : "=r"(p01) : "r"(h01));
                        asm("ex2.approx.f16x2 %0, %1;" : "=r"(p23) : "r"(h23));
                        pf[mt][nt >> 1][(nt & 1) * 2 + 0] = p01;
                        pf[mt][nt >> 1][(nt & 1) * 2 + 1] = p23;
                    }
                }

                // O += P @ V for both row groups off one V-fragment load
                {
                    const uint32_t vB = vB0 + cur * stB + sub * subB;
                    #pragma unroll
                    for (int kp2 = 0; kp2 < 4; kp2++) {
                        uint32_t vf[8][2];
                        #pragma unroll
                        for (int np = 0; np < 4; np++)
                            LDSM_X4_T(vf[np*2][0], vf[np*2][1], vf[np*2+1][0], vf[np*2+1][1],
                                      vB + (uint32_t)((kp2 * 16 * AST + np * 16) * 2));
                        #pragma unroll
                        for (int mt = 0; mt < 2; mt++) {
                            #pragma unroll
                            for (int nt = 0; nt < 8; nt++)
                                mma_h(o[mt][nt], pf[mt][kp2], vf[nt]);
                            mma_h(rsacc[mt], pf[mt][kp2], onesb);
                        }
                    }
                }
            }
        }

        const float nmask = (float)(SEQ - ktEnd * 64);

        #pragma unroll
        for (int mt = 0; mt < 2; mt++) {
            // masked-tile contribution (P==1): suffix column sums of V
            #pragma unroll
            for (int nt = 0; nt < 8; nt++) {
                #pragma unroll
                for (int c2 = 0; c2 < 2; c2++) {
                    float sv = suf[nt * 8 + tg * 2 + c2];
                    o[mt][nt][c2]     += sv;
                    o[mt][nt][2 + c2] += sv;
                }
            }

            const float inv0 = 1.0f / (rsacc[mt][0] + nmask);
            const float inv1 = 1.0f / (rsacc[mt][2] + nmask);

            // normalize + scatter fp16 into scrambled layout:
            // [b,h,s,dh] -> ao[b][2c + (s>>10)][s & 1023], c = h*64+dh
            const int s0 = q0 + wid * 32 + mt * 16 + g, s1 = s0 + 8;
            #pragma unroll
            for (int nt = 0; nt < 8; nt++) {
                #pragma unroll
                for (int c2 = 0; c2 < 2; c2++) {
                    int dh = nt * 8 + tg * 2 + c2;
                    int c  = h * 64 + dh;
                    size_t rowb = (size_t)b * SEQ * DIM;
                    ao[rowb + (size_t)(2*c + (s0 >> 10)) * DIM + (s0 & 1023)] =
                        __float2half(o[mt][nt][c2] * inv0);
                    ao[rowb + (size_t)(2*c + (s1 >> 10)) * DIM + (s1 & 1023)] =
                        __float2half(o[mt][nt][2 + c2] * inv1);
                }
            }
        }
    }
}

// ---------------------------------------------------------------------------
extern "C" void kernel_launch(void* const* d_in, const int* in_sizes, int n_in,
                              void* d_out, int out_size)
{
    const float* x  = (const float*)d_in[0];
    const float* Wq = (const float*)d_in[2];
    const float* bq = (const float*)d_in[3];
    const float* Wk = (const float*)d_in[4];
    const float* bk = (const float*)d_in[5];
    const float* Wv = (const float*)d_in[6];
    const float* bv = (const float*)d_in[7];
    const float* Wo = (const float*)d_in[8];
    const float* bo = (const float*)d_in[9];
    float* out = (float*)d_out;

    __half *xh, *wh, *q, *k, *v, *aoh;
    float *ts;
    cudaGetSymbolAddress((void**)&xh,  g_xh);
    cudaGetSymbolAddress((void**)&wh,  g_wh);
    cudaGetSymbolAddress((void**)&q,   g_q);
    cudaGetSymbolAddress((void**)&k,   g_k);
    cudaGetSymbolAddress((void**)&v,   g_v);
    cudaGetSymbolAddress((void**)&aoh, g_aoh);
    cudaGetSymbolAddress((void**)&ts,  g_tsum);

    cudaFuncSetAttribute(gemm_h, cudaFuncAttributeMaxDynamicSharedMemorySize, GSMEM);
    cudaFuncSetAttribute(attn_h, cudaFuncAttributeMaxDynamicSharedMemorySize, ASMEM);

    convert_h<<<4096, 256>>>(x, Wq, Wk, Wv, Wo, xh, wh);

    // fused QKV projections (thin-warp GEMM, best measured)
    dim3 gg(DIM / 128, MTOT / 128, 3);   // (8, 32, 3)
    gemm_h<<<gg, 256, GSMEM>>>(xh, wh, bq, bk, bv, q, k, v, nullptr, 0);

    dim3 gt(32, BATCH * HEADS);          // per-tile V column sums
    tilesum_k<<<gt, 64>>>(v, ts);

    // fat-warp attention (best measured)
    attn_h<<<NCTA_A, 128, ASMEM>>>(q, k, v, ts, aoh);

    // output projection (f32 out)
    dim3 go(DIM / 128, MTOT / 128, 1);
    gemm_h<<<go, 256, GSMEM>>>(aoh, wh + 3 * (size_t)DIM * DIM,
                               bo, bo, bo, q, q, q, out, 1);
}